// round 1
// baseline (speedup 1.0000x reference)
#include <cuda_runtime.h>
#include <float.h>

#define NB   32      // batches
#define DX   128
#define DY   128
#define DZ   64
#define KTOP 10
#define YT   16      // y-tile per block
#define XT   64      // x-chunk per block

// Per-batch global top-K slots (sortable 64-bit keys). Zeroed each launch.
__device__ unsigned long long gTop[NB][KTOP];

__global__ void init_top_kernel() {
    int i = threadIdx.x;
    if (i < NB * KTOP) ((unsigned long long*)gTop)[i] = 0ULL;
}

__device__ __forceinline__ float4 fmax4(float4 a, float4 b) {
    return make_float4(fmaxf(a.x, b.x), fmaxf(a.y, b.y),
                       fmaxf(a.z, b.z), fmaxf(a.w, b.w));
}

// Replace-min top-K insert via CAS. Returns value of (evicted or current) min
// as a conservative lower bound for the caller's threshold register.
__device__ __forceinline__ float insert_topk(unsigned long long* slots,
                                             unsigned long long key) {
    for (;;) {
        int mi = 0;
        unsigned long long mv = slots[0];
#pragma unroll
        for (int i = 1; i < KTOP; i++) {
            unsigned long long v = slots[i];
            if (v < mv) { mv = v; mi = i; }
        }
        if (key <= mv) return __uint_as_float((unsigned)(mv >> 32));
        if (atomicCAS(&slots[mi], mv, key) == mv)
            return __uint_as_float((unsigned)(mv >> 32));
    }
}

__global__ __launch_bounds__(256)
void peaks_kernel(const float* __restrict__ in) {
    __shared__ float4 raw4[YT + 2][DZ / 4];       // plane being loaded (18 rows)
    __shared__ float4 zm4[YT + 2][DZ / 4];        // z-window max of that plane
    __shared__ float4 yzm4[3][YT][DZ / 4];        // rolling yz-window max, 3 x-planes
    __shared__ float4 rawC4[3][YT][DZ / 4];       // rolling raw center rows
    __shared__ unsigned long long sTop[KTOP];

    const int tx = threadIdx.x;                   // z chunk 0..15 (float4)
    const int ty = threadIdx.y;                   // row in tile 0..15
    const int tid = ty * 16 + tx;
    const int b = blockIdx.z;
    const int y0 = blockIdx.x * YT;
    const int xout0 = blockIdx.y * XT;

    if (tid < KTOP) sTop[tid] = 0ULL;
    __syncthreads();

    const float4* in4 = (const float4*)(in + (size_t)b * DX * DY * DZ);
    float thresh = 0.0f;

    for (int xp = xout0 - 1; xp <= xout0 + XT; xp++) {
        // ---- load plane xp, rows y0-1 .. y0+16 (OOB -> -FLT_MAX) ----
        const bool xin = (xp >= 0 && xp < DX);
        for (int i = tid; i < (YT + 2) * (DZ / 4); i += 256) {
            int r = i >> 4, zc = i & 15;
            int gy = y0 - 1 + r;
            float4 v;
            if (xin && gy >= 0 && gy < DY)
                v = in4[((size_t)xp * DY + gy) * (DZ / 4) + zc];
            else
                v = make_float4(-FLT_MAX, -FLT_MAX, -FLT_MAX, -FLT_MAX);
            raw4[r][zc] = v;
        }
        __syncthreads();

        // ---- z-window max ----
        for (int i = tid; i < (YT + 2) * (DZ / 4); i += 256) {
            int r = i >> 4, zc = i & 15;
            float4 c = raw4[r][zc];
            float l = (zc > 0)  ? raw4[r][zc - 1].w : -FLT_MAX;
            float rr = (zc < 15) ? raw4[r][zc + 1].x : -FLT_MAX;
            float4 m;
            m.x = fmaxf(fmaxf(l,   c.x), c.y);
            m.y = fmaxf(fmaxf(c.x, c.y), c.z);
            m.z = fmaxf(fmaxf(c.y, c.z), c.w);
            m.w = fmaxf(fmaxf(c.z, c.w), rr);
            zm4[r][zc] = m;
        }
        __syncthreads();

        // ---- y-window max into rolling slot; keep raw center rows ----
        const int s = (xp + 1) % 3;   // xp >= -1 so xp+1 >= 0
        {
            float4 m = fmax4(zm4[ty][tx], fmax4(zm4[ty + 1][tx], zm4[ty + 2][tx]));
            yzm4[s][ty][tx] = m;
            rawC4[s][ty][tx] = raw4[ty + 1][tx];
        }
        __syncthreads();

        // ---- output plane xc = xp-1: pooled = max over 3 x slots ----
        const int xc = xp - 1;
        if (xc >= xout0 && xc < xout0 + XT) {
            const int s0 = xc % 3, s1 = (xc + 1) % 3, s2 = (xc + 2) % 3;
            float4 m = fmax4(yzm4[s0][ty][tx],
                             fmax4(yzm4[s1][ty][tx], yzm4[s2][ty][tx]));
            float4 c = rawC4[s1][ty][tx];
            const int gy = y0 + ty;
            const unsigned base = (unsigned)((xc * DY + gy) * DZ + tx * 4);
            if (c.x > thresh && c.x == m.x)
                thresh = insert_topk(sTop, ((unsigned long long)__float_as_uint(c.x) << 32) |
                                           (unsigned long long)(0xFFFFFFFFu - (base + 0)));
            if (c.y > thresh && c.y == m.y)
                thresh = insert_topk(sTop, ((unsigned long long)__float_as_uint(c.y) << 32) |
                                           (unsigned long long)(0xFFFFFFFFu - (base + 1)));
            if (c.z > thresh && c.z == m.z)
                thresh = insert_topk(sTop, ((unsigned long long)__float_as_uint(c.z) << 32) |
                                           (unsigned long long)(0xFFFFFFFFu - (base + 2)));
            if (c.w > thresh && c.w == m.w)
                thresh = insert_topk(sTop, ((unsigned long long)__float_as_uint(c.w) << 32) |
                                           (unsigned long long)(0xFFFFFFFFu - (base + 3)));
        }
    }

    __syncthreads();
    if (tid < KTOP) {
        unsigned long long key = sTop[tid];
        if (key) insert_topk(&gTop[b][0], key);
    }
}

__global__ void finalize_kernel(float* __restrict__ out) {
    int b = threadIdx.x;
    if (b >= NB) return;

    unsigned long long k[KTOP];
#pragma unroll
    for (int i = 0; i < KTOP; i++) k[i] = gTop[b][i];

    // selection sort, descending (10 elements)
#pragma unroll
    for (int i = 0; i < KTOP; i++) {
        int mi = i;
#pragma unroll
        for (int j = i + 1; j < KTOP; j++)
            if (k[j] > k[mi]) mi = j;
        unsigned long long t = k[i]; k[i] = k[mi]; k[mi] = t;
    }

    float* o = out + (size_t)b * KTOP * 5;
#pragma unroll
    for (int i = 0; i < KTOP; i++) {
        float v = __uint_as_float((unsigned)(k[i] >> 32));
        unsigned idx = 0xFFFFFFFFu - (unsigned)(k[i] & 0xFFFFFFFFull);
        int ix = (int)(idx / (DY * DZ));
        int iy = (int)((idx / DZ) % DY);
        int iz = (int)(idx % DZ);
        float lx = (float)ix / 127.0f * 8000.0f - 4000.0f;
        float ly = (float)iy / 127.0f * 8000.0f - 4000.0f;
        float lz = (float)iz / 63.0f * 2000.0f - 700.0f;   // + 300 - 1000
        float conf = (v > 0.3f) ? 0.0f : -1.0f;
        o[i * 5 + 0] = lx;
        o[i * 5 + 1] = ly;
        o[i * 5 + 2] = lz;
        o[i * 5 + 3] = conf;
        o[i * 5 + 4] = v;
    }
}

extern "C" void kernel_launch(void* const* d_in, const int* in_sizes, int n_in,
                              void* d_out, int out_size) {
    const float* in = (const float*)d_in[0];
    float* out = (float*)d_out;

    init_top_kernel<<<1, NB * KTOP>>>();
    dim3 grid(DY / YT, DX / XT, NB);   // (8, 2, 32) = 512 blocks
    peaks_kernel<<<grid, dim3(16, 16)>>>(in);
    finalize_kernel<<<1, 32>>>(out);
}